// round 1
// baseline (speedup 1.0000x reference)
#include <cuda_runtime.h>
#include <math.h>

#define Bq   16
#define Sq   512
#define Dq   768
#define Hq   12
#define HDq  64
#define Lq   4
#define Fq   3072
#define NK   9
#define D3   2304          // 3*D
#define Mtok (Bq*Sq)       // 8192 tokens

// ---------------- scratch (static device globals; no allocation) ----------------
__device__ float g_x   [Mtok * Dq];                    // activations
__device__ float g_qkv [Mtok * D3];                    // qkv projections
__device__ float g_att [(size_t)Bq * Hq * Sq * Sq];    // attention probs
__device__ float g_ctx [Mtok * Dq];                    // attention context
__device__ float g_proj[Mtok * Dq];                    // proj / W2 output
__device__ float g_h   [Mtok * Fq];                    // MLP hidden
__device__ float g_lg  [Mtok * NK];                    // logits
__device__ float g_sc  [Bq];                           // per-batch gold score

// ---------------- reductions ----------------
__device__ __forceinline__ float block_reduce_sum(float v, float* scratch) {
    __syncthreads();
    int lane = threadIdx.x & 31, wid = threadIdx.x >> 5;
    #pragma unroll
    for (int o = 16; o > 0; o >>= 1) v += __shfl_down_sync(0xffffffffu, v, o);
    if (lane == 0) scratch[wid] = v;
    __syncthreads();
    if (wid == 0) {
        int nw = (blockDim.x + 31) >> 5;
        float r = (lane < nw) ? scratch[lane] : 0.f;
        #pragma unroll
        for (int o = 16; o > 0; o >>= 1) r += __shfl_down_sync(0xffffffffu, r, o);
        if (lane == 0) scratch[0] = r;
    }
    __syncthreads();
    return scratch[0];
}

__device__ __forceinline__ float block_reduce_max(float v, float* scratch) {
    __syncthreads();
    int lane = threadIdx.x & 31, wid = threadIdx.x >> 5;
    #pragma unroll
    for (int o = 16; o > 0; o >>= 1) v = fmaxf(v, __shfl_down_sync(0xffffffffu, v, o));
    if (lane == 0) scratch[wid] = v;
    __syncthreads();
    if (wid == 0) {
        int nw = (blockDim.x + 31) >> 5;
        float r = (lane < nw) ? scratch[lane] : -INFINITY;
        #pragma unroll
        for (int o = 16; o > 0; o >>= 1) r = fmaxf(r, __shfl_down_sync(0xffffffffu, r, o));
        if (lane == 0) scratch[0] = r;
    }
    __syncthreads();
    return scratch[0];
}

// ---------------- embedding + layernorm ----------------
__global__ void embed_ln_kernel(const int* __restrict__ ids,
                                const float* __restrict__ emb,
                                const float* __restrict__ pos,
                                const float* __restrict__ g,
                                const float* __restrict__ bta,
                                float* __restrict__ x) {
    int row = blockIdx.x;
    int s = row % Sq;
    __shared__ float buf[Dq];
    __shared__ float scratch[32];
    int tok = ids[row];
    for (int d = threadIdx.x; d < Dq; d += blockDim.x)
        buf[d] = emb[(size_t)tok * Dq + d] + pos[s * Dq + d];
    float ls = 0.f;
    for (int d = threadIdx.x; d < Dq; d += blockDim.x) ls += buf[d];
    float mean = block_reduce_sum(ls, scratch) * (1.0f / Dq);
    float lv = 0.f;
    for (int d = threadIdx.x; d < Dq; d += blockDim.x) { float t = buf[d] - mean; lv += t * t; }
    float var = block_reduce_sum(lv, scratch) * (1.0f / Dq);
    float rstd = rsqrtf(var + 1e-12f);
    for (int d = threadIdx.x; d < Dq; d += blockDim.x)
        x[(size_t)row * Dq + d] = (buf[d] - mean) * rstd * g[d] + bta[d];
}

// ---------------- residual add + layernorm ----------------
__global__ void add_ln_kernel(const float* __restrict__ xin,
                              const float* __restrict__ proj,
                              const float* __restrict__ g,
                              const float* __restrict__ bta,
                              float* __restrict__ xout) {
    int row = blockIdx.x;
    __shared__ float buf[Dq];
    __shared__ float scratch[32];
    for (int d = threadIdx.x; d < Dq; d += blockDim.x)
        buf[d] = xin[(size_t)row * Dq + d] + proj[(size_t)row * Dq + d];
    float ls = 0.f;
    for (int d = threadIdx.x; d < Dq; d += blockDim.x) ls += buf[d];
    float mean = block_reduce_sum(ls, scratch) * (1.0f / Dq);
    float lv = 0.f;
    for (int d = threadIdx.x; d < Dq; d += blockDim.x) { float t = buf[d] - mean; lv += t * t; }
    float var = block_reduce_sum(lv, scratch) * (1.0f / Dq);
    float rstd = rsqrtf(var + 1e-12f);
    for (int d = threadIdx.x; d < Dq; d += blockDim.x)
        xout[(size_t)row * Dq + d] = (buf[d] - mean) * rstd * g[d] + bta[d];
}

// ---------------- generic 64x64x16 fp32 GEMM: C = A[MxK] * W[KxN] + bias, opt GELU ----------------
__global__ void gemm64(const float* __restrict__ A, const float* __restrict__ W,
                       const float* __restrict__ bias, float* __restrict__ C,
                       int M, int N, int Kd, int act) {
    __shared__ float As[16][64];
    __shared__ float Bs[16][64];
    int tid = threadIdx.x;
    int tx = tid & 15, ty = tid >> 4;
    int row0 = blockIdx.y << 6, col0 = blockIdx.x << 6;
    float acc[4][4] = {};
    for (int k0 = 0; k0 < Kd; k0 += 16) {
        #pragma unroll
        for (int i = 0; i < 4; i++) {
            int idx = tid + (i << 8);
            int kk = idx & 15, mm = idx >> 4;
            As[kk][mm] = A[(size_t)(row0 + mm) * Kd + k0 + kk];
        }
        #pragma unroll
        for (int i = 0; i < 4; i++) {
            int idx = tid + (i << 8);
            int nn = idx & 63, kk = idx >> 6;
            Bs[kk][nn] = W[(size_t)(k0 + kk) * N + col0 + nn];
        }
        __syncthreads();
        #pragma unroll
        for (int kk = 0; kk < 16; kk++) {
            float a[4], b[4];
            #pragma unroll
            for (int i = 0; i < 4; i++) a[i] = As[kk][ty + (i << 4)];
            #pragma unroll
            for (int j = 0; j < 4; j++) b[j] = Bs[kk][tx + (j << 4)];
            #pragma unroll
            for (int i = 0; i < 4; i++)
                #pragma unroll
                for (int j = 0; j < 4; j++)
                    acc[i][j] += a[i] * b[j];
        }
        __syncthreads();
    }
    #pragma unroll
    for (int i = 0; i < 4; i++) {
        int r = row0 + ty + (i << 4);
        #pragma unroll
        for (int j = 0; j < 4; j++) {
            int c = col0 + tx + (j << 4);
            float v = acc[i][j] + bias[c];
            if (act) {
                float u = v;
                float inner = 0.7978845608028654f * (u + 0.044715f * u * u * u);
                v = 0.5f * u * (1.0f + tanhf(inner));
            }
            C[(size_t)r * N + c] = v;
        }
    }
}

// ---------------- attention scores: att[b,h,q,t] = q.k/8 + maskbias ----------------
__global__ void attn_scores_kernel(const float* __restrict__ qkv,
                                   const int* __restrict__ mask,
                                   float* __restrict__ att) {
    int bh = blockIdx.z;
    int b = bh / Hq, h = bh % Hq;
    int q0 = blockIdx.y << 6, t0 = blockIdx.x << 6;
    const float* qb = qkv + (size_t)b * Sq * D3 + h * HDq;
    const float* kb = qkv + (size_t)b * Sq * D3 + Dq + h * HDq;
    __shared__ float Qs[64][65];
    __shared__ float Ks[64][65];
    int tid = threadIdx.x;
    #pragma unroll
    for (int i = 0; i < 16; i++) {
        int idx = tid + (i << 8);
        int d = idx & 63, r = idx >> 6;
        Qs[r][d] = qb[(size_t)(q0 + r) * D3 + d];
        Ks[r][d] = kb[(size_t)(t0 + r) * D3 + d];
    }
    __syncthreads();
    int tx = tid & 15, ty = tid >> 4;
    float acc[4][4] = {};
    #pragma unroll 8
    for (int kk = 0; kk < 64; kk++) {
        float a[4], bb[4];
        #pragma unroll
        for (int i = 0; i < 4; i++) a[i] = Qs[ty + (i << 4)][kk];
        #pragma unroll
        for (int j = 0; j < 4; j++) bb[j] = Ks[tx + (j << 4)][kk];
        #pragma unroll
        for (int i = 0; i < 4; i++)
            #pragma unroll
            for (int j = 0; j < 4; j++)
                acc[i][j] += a[i] * bb[j];
    }
    #pragma unroll
    for (int j = 0; j < 4; j++) {
        int t = t0 + tx + (j << 4);
        float biasv = (1.0f - (float)mask[b * Sq + t]) * -1e9f;
        #pragma unroll
        for (int i = 0; i < 4; i++) {
            int q = q0 + ty + (i << 4);
            att[((size_t)bh * Sq + q) * Sq + t] = acc[i][j] * 0.125f + biasv;
        }
    }
}

// ---------------- row softmax over 512 ----------------
__global__ void softmax512_kernel(float* __restrict__ att) {
    size_t row = blockIdx.x;
    float* p = att + row * Sq;
    int tid = threadIdx.x;   // 128 threads
    __shared__ float scratch[32];
    float v[4];
    float m = -INFINITY;
    #pragma unroll
    for (int i = 0; i < 4; i++) { v[i] = p[tid + i * 128]; m = fmaxf(m, v[i]); }
    m = block_reduce_max(m, scratch);
    float s = 0.f;
    #pragma unroll
    for (int i = 0; i < 4; i++) { v[i] = __expf(v[i] - m); s += v[i]; }
    s = block_reduce_sum(s, scratch);
    float inv = 1.0f / s;
    #pragma unroll
    for (int i = 0; i < 4; i++) p[tid + i * 128] = v[i] * inv;
}

// ---------------- context: ctx[b,q, h*64+d] = sum_t att * v ----------------
__global__ void attn_ctx_kernel(const float* __restrict__ att,
                                const float* __restrict__ qkv,
                                float* __restrict__ ctx) {
    int bh = blockIdx.y;
    int b = bh / Hq, h = bh % Hq;
    int q0 = blockIdx.x << 6;
    const float* A = att + (size_t)bh * Sq * Sq;
    const float* vb = qkv + (size_t)b * Sq * D3 + 2 * Dq + h * HDq;
    __shared__ float As[16][64];
    __shared__ float Vs[16][64];
    int tid = threadIdx.x;
    int tx = tid & 15, ty = tid >> 4;
    float acc[4][4] = {};
    for (int t0 = 0; t0 < Sq; t0 += 16) {
        #pragma unroll
        for (int i = 0; i < 4; i++) {
            int idx = tid + (i << 8);
            int kk = idx & 15, mm = idx >> 4;
            As[kk][mm] = A[(size_t)(q0 + mm) * Sq + t0 + kk];
            int nn = idx & 63, k2 = idx >> 6;
            Vs[k2][nn] = vb[(size_t)(t0 + k2) * D3 + nn];
        }
        __syncthreads();
        #pragma unroll
        for (int kk = 0; kk < 16; kk++) {
            float a[4], bb[4];
            #pragma unroll
            for (int i = 0; i < 4; i++) a[i] = As[kk][ty + (i << 4)];
            #pragma unroll
            for (int j = 0; j < 4; j++) bb[j] = Vs[kk][tx + (j << 4)];
            #pragma unroll
            for (int i = 0; i < 4; i++)
                #pragma unroll
                for (int j = 0; j < 4; j++)
                    acc[i][j] += a[i] * bb[j];
        }
        __syncthreads();
    }
    #pragma unroll
    for (int i = 0; i < 4; i++) {
        int q = q0 + ty + (i << 4);
        #pragma unroll
        for (int j = 0; j < 4; j++)
            ctx[((size_t)b * Sq + q) * Dq + h * HDq + tx + (j << 4)] = acc[i][j];
    }
}

// ---------------- logits: x[Mtok,768] @ Wcls[768,9] + bcls ----------------
__global__ void logits_kernel(const float* __restrict__ x,
                              const float* __restrict__ Wc,
                              const float* __restrict__ bc,
                              float* __restrict__ lg) {
    int row = blockIdx.x;
    __shared__ float buf[Dq];
    for (int d = threadIdx.x; d < Dq; d += blockDim.x)
        buf[d] = x[(size_t)row * Dq + d];
    __syncthreads();
    int w = threadIdx.x >> 5, lane = threadIdx.x & 31;  // 9 warps
    if (w < NK) {
        float s = 0.f;
        for (int d = lane; d < Dq; d += 32) s += buf[d] * Wc[d * NK + w];
        #pragma unroll
        for (int o = 16; o > 0; o >>= 1) s += __shfl_down_sync(0xffffffffu, s, o);
        if (lane == 0) lg[(size_t)row * NK + w] = s + bc[w];
    }
}

// ---------------- CRF gold-path score per batch ----------------
__global__ void crf_score_kernel(const float* __restrict__ lg,
                                 const int* __restrict__ labels,
                                 const int* __restrict__ mask,
                                 const float* __restrict__ st,
                                 const float* __restrict__ en,
                                 const float* __restrict__ tr,
                                 float* __restrict__ sc) {
    int b = blockIdx.x;
    const int* lab = labels + b * Sq;
    const int* mk = mask + b * Sq;
    __shared__ float scratch[32];
    float lsum = 0.f; float lcnt = 0.f;
    for (int t = threadIdx.x; t < Sq; t += blockDim.x) {
        lcnt += (float)mk[t];
        if (t >= 1) {
            float e = lg[((size_t)b * Sq + t) * NK + lab[t]];
            float trv = tr[lab[t - 1] * NK + lab[t]];
            lsum += (float)mk[t] * (trv + e);
        }
    }
    float tot = block_reduce_sum(lsum, scratch);
    float cnt = block_reduce_sum(lcnt, scratch);
    if (threadIdx.x == 0) {
        int last = (int)(cnt + 0.5f) - 1;
        sc[b] = st[lab[0]] + lg[((size_t)b * Sq) * NK + lab[0]] + tot + en[lab[last]];
    }
}

// ---------------- CRF forward (logZ) + final scalar ----------------
__global__ void crf_forward_kernel(const float* __restrict__ lg,
                                   const int* __restrict__ mask,
                                   const float* __restrict__ st,
                                   const float* __restrict__ en,
                                   const float* __restrict__ tr,
                                   const float* __restrict__ sc,
                                   float* __restrict__ out) {
    __shared__ float sal[Bq][12];
    __shared__ float strn[NK * NK];
    __shared__ float sst[NK], sen[NK];
    __shared__ float slz[Bq];
    int tid = threadIdx.x;  // 512 threads = 16 warps, one per batch
    if (tid < NK * NK) strn[tid] = tr[tid];
    if (tid < NK) { sst[tid] = st[tid]; sen[tid] = en[tid]; }
    __syncthreads();
    int b = tid >> 5, j = tid & 31;
    int jj = (j < NK) ? j : 0;
    if (j < NK) sal[b][j] = sst[j] + lg[((size_t)b * Sq) * NK + j];
    __syncwarp();
    for (int t = 1; t < Sq; t++) {
        float a[NK];
        #pragma unroll
        for (int i = 0; i < NK; i++) a[i] = sal[b][i];
        float m = -INFINITY;
        #pragma unroll
        for (int i = 0; i < NK; i++) m = fmaxf(m, a[i] + strn[i * NK + jj]);
        float s = 0.f;
        #pragma unroll
        for (int i = 0; i < NK; i++) s += expf(a[i] + strn[i * NK + jj] - m);
        float nxt = m + logf(s) + lg[((size_t)b * Sq + t) * NK + jj];
        int mt = mask[b * Sq + t];
        float newv = (mt > 0) ? nxt : a[jj];
        __syncwarp();
        if (j < NK) sal[b][j] = newv;
        __syncwarp();
    }
    float v = (j < NK) ? (sal[b][jj] + sen[jj]) : -INFINITY;
    float m = v;
    #pragma unroll
    for (int o = 16; o > 0; o >>= 1) m = fmaxf(m, __shfl_xor_sync(0xffffffffu, m, o));
    float s = (j < NK) ? expf(v - m) : 0.f;
    #pragma unroll
    for (int o = 16; o > 0; o >>= 1) s += __shfl_xor_sync(0xffffffffu, s, o);
    if (j == 0) slz[b] = m + logf(s);
    __syncthreads();
    if (tid == 0) {
        float o = 0.f;
        for (int b2 = 0; b2 < Bq; b2++) o += slz[b2] - sc[b2];
        out[0] = o;
    }
}

// ---------------- host launch ----------------
extern "C" void kernel_launch(void* const* d_in, const int* in_sizes, int n_in,
                              void* d_out, int out_size) {
    const int*   input_ids = (const int*)d_in[0];
    const int*   amask     = (const int*)d_in[1];
    const int*   labels    = (const int*)d_in[2];
    const float* emb   = (const float*)d_in[3];
    const float* pos   = (const float*)d_in[4];
    const float* lng   = (const float*)d_in[5];
    const float* lnb   = (const float*)d_in[6];
    const float* Wqkv  = (const float*)d_in[7];
    const float* bqkv  = (const float*)d_in[8];
    const float* Wo    = (const float*)d_in[9];
    const float* bo    = (const float*)d_in[10];
    const float* ln1g  = (const float*)d_in[11];
    const float* ln1b  = (const float*)d_in[12];
    const float* W1    = (const float*)d_in[13];
    const float* b1    = (const float*)d_in[14];
    const float* W2    = (const float*)d_in[15];
    const float* b2    = (const float*)d_in[16];
    const float* ln2g  = (const float*)d_in[17];
    const float* ln2b  = (const float*)d_in[18];
    const float* Wcls  = (const float*)d_in[19];
    const float* bcls  = (const float*)d_in[20];
    const float* st    = (const float*)d_in[21];
    const float* en    = (const float*)d_in[22];
    const float* tr    = (const float*)d_in[23];
    float* out = (float*)d_out;

    float *x, *qkv, *att, *ctx, *proj, *hbuf, *lg, *sc;
    cudaGetSymbolAddress((void**)&x,    g_x);
    cudaGetSymbolAddress((void**)&qkv,  g_qkv);
    cudaGetSymbolAddress((void**)&att,  g_att);
    cudaGetSymbolAddress((void**)&ctx,  g_ctx);
    cudaGetSymbolAddress((void**)&proj, g_proj);
    cudaGetSymbolAddress((void**)&hbuf, g_h);
    cudaGetSymbolAddress((void**)&lg,   g_lg);
    cudaGetSymbolAddress((void**)&sc,   g_sc);

    embed_ln_kernel<<<Mtok, 256>>>(input_ids, emb, pos, lng, lnb, x);

    for (int l = 0; l < Lq; l++) {
        gemm64<<<dim3(D3 / 64, Mtok / 64), 256>>>(
            x, Wqkv + (size_t)l * Dq * D3, bqkv + l * D3, qkv, Mtok, D3, Dq, 0);
        attn_scores_kernel<<<dim3(Sq / 64, Sq / 64, Bq * Hq), 256>>>(qkv, amask, att);
        softmax512_kernel<<<Bq * Hq * Sq, 128>>>(att);
        attn_ctx_kernel<<<dim3(Sq / 64, Bq * Hq), 256>>>(att, qkv, ctx);
        gemm64<<<dim3(Dq / 64, Mtok / 64), 256>>>(
            ctx, Wo + (size_t)l * Dq * Dq, bo + l * Dq, proj, Mtok, Dq, Dq, 0);
        add_ln_kernel<<<Mtok, 256>>>(x, proj, ln1g + l * Dq, ln1b + l * Dq, x);
        gemm64<<<dim3(Fq / 64, Mtok / 64), 256>>>(
            x, W1 + (size_t)l * Dq * Fq, b1 + l * Fq, hbuf, Mtok, Fq, Dq, 1);
        gemm64<<<dim3(Dq / 64, Mtok / 64), 256>>>(
            hbuf, W2 + (size_t)l * Fq * Dq, b2 + l * Dq, proj, Mtok, Dq, Fq, 0);
        add_ln_kernel<<<Mtok, 256>>>(x, proj, ln2g + l * Dq, ln2b + l * Dq, x);
    }

    logits_kernel<<<Mtok, 288>>>(x, Wcls, bcls, lg);
    crf_score_kernel<<<Bq, 256>>>(lg, labels, amask, st, en, tr, sc);
    crf_forward_kernel<<<1, 512>>>(lg, amask, st, en, tr, sc, out);
}

// round 4
// speedup vs baseline: 4.0968x; 4.0968x over previous
#include <cuda_runtime.h>
#include <cuda_bf16.h>
#include <cstdint>
#include <math.h>

#define Bq   16
#define Sq   512
#define Dq   768
#define Hq   12
#define HDq  64
#define Lq   4
#define Fq   3072
#define NK   9
#define D3   2304          // 3*D
#define Mtok (Bq*Sq)       // 8192 tokens

// ---------------- scratch (static device globals; no allocation) ----------------
__device__ float g_x   [Mtok * Dq];                    // activations
__device__ float g_qkv [Mtok * D3];                    // qkv projections
__device__ float g_att [(size_t)Bq * Hq * Sq * Sq];    // attention probs
__device__ float g_ctx [Mtok * Dq];                    // attention context
__device__ float g_proj[Mtok * Dq];                    // proj / W2 output
__device__ float g_h   [Mtok * Fq];                    // MLP hidden
__device__ float g_lg  [Mtok * NK];                    // logits
__device__ float g_sc  [Bq];                           // per-batch gold score

// ---------------- reductions ----------------
__device__ __forceinline__ float block_reduce_sum(float v, float* scratch) {
    __syncthreads();
    int lane = threadIdx.x & 31, wid = threadIdx.x >> 5;
    #pragma unroll
    for (int o = 16; o > 0; o >>= 1) v += __shfl_down_sync(0xffffffffu, v, o);
    if (lane == 0) scratch[wid] = v;
    __syncthreads();
    if (wid == 0) {
        int nw = (blockDim.x + 31) >> 5;
        float r = (lane < nw) ? scratch[lane] : 0.f;
        #pragma unroll
        for (int o = 16; o > 0; o >>= 1) r += __shfl_down_sync(0xffffffffu, r, o);
        if (lane == 0) scratch[0] = r;
    }
    __syncthreads();
    return scratch[0];
}

__device__ __forceinline__ float block_reduce_max(float v, float* scratch) {
    __syncthreads();
    int lane = threadIdx.x & 31, wid = threadIdx.x >> 5;
    #pragma unroll
    for (int o = 16; o > 0; o >>= 1) v = fmaxf(v, __shfl_down_sync(0xffffffffu, v, o));
    if (lane == 0) scratch[wid] = v;
    __syncthreads();
    if (wid == 0) {
        int nw = (blockDim.x + 31) >> 5;
        float r = (lane < nw) ? scratch[lane] : -INFINITY;
        #pragma unroll
        for (int o = 16; o > 0; o >>= 1) r = fmaxf(r, __shfl_down_sync(0xffffffffu, r, o));
        if (lane == 0) scratch[0] = r;
    }
    __syncthreads();
    return scratch[0];
}

// ---------------- embedding + layernorm ----------------
__global__ void embed_ln_kernel(const int* __restrict__ ids,
                                const float* __restrict__ emb,
                                const float* __restrict__ pos,
                                const float* __restrict__ g,
                                const float* __restrict__ bta,
                                float* __restrict__ x) {
    int row = blockIdx.x;
    int s = row % Sq;
    __shared__ float buf[Dq];
    __shared__ float scratch[32];
    int tok = ids[row];
    for (int d = threadIdx.x; d < Dq; d += blockDim.x)
        buf[d] = emb[(size_t)tok * Dq + d] + pos[s * Dq + d];
    float ls = 0.f;
    for (int d = threadIdx.x; d < Dq; d += blockDim.x) ls += buf[d];
    float mean = block_reduce_sum(ls, scratch) * (1.0f / Dq);
    float lv = 0.f;
    for (int d = threadIdx.x; d < Dq; d += blockDim.x) { float t = buf[d] - mean; lv += t * t; }
    float var = block_reduce_sum(lv, scratch) * (1.0f / Dq);
    float rstd = rsqrtf(var + 1e-12f);
    for (int d = threadIdx.x; d < Dq; d += blockDim.x)
        x[(size_t)row * Dq + d] = (buf[d] - mean) * rstd * g[d] + bta[d];
}

// ---------------- residual add + layernorm ----------------
__global__ void add_ln_kernel(const float* __restrict__ xin,
                              const float* __restrict__ proj,
                              const float* __restrict__ g,
                              const float* __restrict__ bta,
                              float* __restrict__ xout) {
    int row = blockIdx.x;
    __shared__ float buf[Dq];
    __shared__ float scratch[32];
    for (int d = threadIdx.x; d < Dq; d += blockDim.x)
        buf[d] = xin[(size_t)row * Dq + d] + proj[(size_t)row * Dq + d];
    float ls = 0.f;
    for (int d = threadIdx.x; d < Dq; d += blockDim.x) ls += buf[d];
    float mean = block_reduce_sum(ls, scratch) * (1.0f / Dq);
    float lv = 0.f;
    for (int d = threadIdx.x; d < Dq; d += blockDim.x) { float t = buf[d] - mean; lv += t * t; }
    float var = block_reduce_sum(lv, scratch) * (1.0f / Dq);
    float rstd = rsqrtf(var + 1e-12f);
    for (int d = threadIdx.x; d < Dq; d += blockDim.x)
        xout[(size_t)row * Dq + d] = (buf[d] - mean) * rstd * g[d] + bta[d];
}

// ================= bf16 tensor-core GEMM =================
// C[M,N] = A[M,K] (fp32, cvt bf16) @ W[K,N] (fp32, cvt bf16) + bias, opt GELU.
// CTA tile 128x128, K-tile 32. 8 warps (2x4), warp tile 64x32. mma.m16n8k16.
#define GBM 128
#define GBN 128
#define GBK 32
#define ASTR 40    // A SMEM row stride (bf16 elems): 32 + 8 pad -> conflict-free ldmatrix
#define BSTR 136   // B SMEM row stride (bf16 elems): 128 + 8 pad

__global__ __launch_bounds__(256) void gemm_bf16(
    const float* __restrict__ A, const float* __restrict__ W,
    const float* __restrict__ bias, float* __restrict__ C,
    int M, int N, int Kd, int act)
{
    __shared__ __nv_bfloat16 As[GBM * ASTR];
    __shared__ __nv_bfloat16 Bs[GBK * BSTR];
    int tid = threadIdx.x;
    int warp = tid >> 5, lane = tid & 31;
    int wm = (warp >> 2) * 64;       // warp M offset within CTA tile
    int wn = (warp & 3) * 32;        // warp N offset
    int row0 = blockIdx.y * GBM, col0 = blockIdx.x * GBN;

    float acc[4][4][4];
    #pragma unroll
    for (int i = 0; i < 4; i++)
        #pragma unroll
        for (int j = 0; j < 4; j++)
            #pragma unroll
            for (int r = 0; r < 4; r++) acc[i][j][r] = 0.f;

    int a_row = tid >> 3;            // 0..31 (+32 per iter)
    int a_col = (tid & 7) * 4;
    int b_row = tid >> 5;            // 0..7 (+8 per iter)
    int b_col = lane * 4;

    for (int k0 = 0; k0 < Kd; k0 += GBK) {
        #pragma unroll
        for (int i = 0; i < 4; i++) {
            int r = a_row + i * 32;
            float4 v = *(const float4*)&A[(size_t)(row0 + r) * Kd + k0 + a_col];
            *(__nv_bfloat162*)&As[r * ASTR + a_col]     = __floats2bfloat162_rn(v.x, v.y);
            *(__nv_bfloat162*)&As[r * ASTR + a_col + 2] = __floats2bfloat162_rn(v.z, v.w);
        }
        #pragma unroll
        for (int i = 0; i < 4; i++) {
            int r = b_row + i * 8;
            float4 v = *(const float4*)&W[(size_t)(k0 + r) * N + col0 + b_col];
            *(__nv_bfloat162*)&Bs[r * BSTR + b_col]     = __floats2bfloat162_rn(v.x, v.y);
            *(__nv_bfloat162*)&Bs[r * BSTR + b_col + 2] = __floats2bfloat162_rn(v.z, v.w);
        }
        __syncthreads();
        #pragma unroll
        for (int ks = 0; ks < 2; ks++) {
            int kk = ks * 16;
            unsigned int af[4][4];
            #pragma unroll
            for (int i = 0; i < 4; i++) {
                int r = wm + i * 16 + (lane & 15);
                int c = kk + 8 * (lane >> 4);
                unsigned int addr = (unsigned int)__cvta_generic_to_shared(&As[r * ASTR + c]);
                asm volatile("ldmatrix.sync.aligned.m8n8.x4.shared.b16 {%0,%1,%2,%3}, [%4];"
                    : "=r"(af[i][0]), "=r"(af[i][1]), "=r"(af[i][2]), "=r"(af[i][3])
                    : "r"(addr));
            }
            unsigned int bfr[4][2];
            #pragma unroll
            for (int j = 0; j < 2; j++) {
                int r = kk + (lane & 7) + 8 * ((lane >> 3) & 1);
                int c = wn + j * 16 + 8 * (lane >> 4);
                unsigned int addr = (unsigned int)__cvta_generic_to_shared(&Bs[r * BSTR + c]);
                asm volatile("ldmatrix.sync.aligned.m8n8.x4.trans.shared.b16 {%0,%1,%2,%3}, [%4];"
                    : "=r"(bfr[2 * j][0]), "=r"(bfr[2 * j][1]),
                      "=r"(bfr[2 * j + 1][0]), "=r"(bfr[2 * j + 1][1])
                    : "r"(addr));
            }
            #pragma unroll
            for (int i = 0; i < 4; i++)
                #pragma unroll
                for (int j = 0; j < 4; j++)
                    asm volatile(
                        "mma.sync.aligned.m16n8k16.row.col.f32.bf16.bf16.f32 "
                        "{%0,%1,%2,%3}, {%4,%5,%6,%7}, {%8,%9}, {%0,%1,%2,%3};"
                        : "+f"(acc[i][j][0]), "+f"(acc[i][j][1]),
                          "+f"(acc[i][j][2]), "+f"(acc[i][j][3])
                        : "r"(af[i][0]), "r"(af[i][1]), "r"(af[i][2]), "r"(af[i][3]),
                          "r"(bfr[j][0]), "r"(bfr[j][1]));
        }
        __syncthreads();
    }

    int g = lane >> 2, q = lane & 3;
    #pragma unroll
    for (int i = 0; i < 4; i++) {
        #pragma unroll
        for (int j = 0; j < 4; j++) {
            int r = row0 + wm + i * 16 + g;
            int c = col0 + wn + j * 8 + q * 2;
            float b0 = bias[c], b1 = bias[c + 1];
            #pragma unroll
            for (int half = 0; half < 2; half++) {
                int rr = r + half * 8;
                float v0 = acc[i][j][half * 2 + 0] + b0;
                float v1 = acc[i][j][half * 2 + 1] + b1;
                if (act) {
                    float in0 = 0.7978845608028654f * (v0 + 0.044715f * v0 * v0 * v0);
                    v0 = 0.5f * v0 * (1.0f + tanhf(in0));
                    float in1 = 0.7978845608028654f * (v1 + 0.044715f * v1 * v1 * v1);
                    v1 = 0.5f * v1 * (1.0f + tanhf(in1));
                }
                *(float2*)&C[(size_t)rr * N + c] = make_float2(v0, v1);
            }
        }
    }
}

// ---------------- attention scores: att[b,h,q,t] = q.k/8 + maskbias ----------------
__global__ void attn_scores_kernel(const float* __restrict__ qkv,
                                   const int* __restrict__ mask,
                                   float* __restrict__ att) {
    int bh = blockIdx.z;
    int b = bh / Hq, h = bh % Hq;
    int q0 = blockIdx.y << 6, t0 = blockIdx.x << 6;
    const float* qb = qkv + (size_t)b * Sq * D3 + h * HDq;
    const float* kb = qkv + (size_t)b * Sq * D3 + Dq + h * HDq;
    __shared__ float Qs[64][65];
    __shared__ float Ks[64][65];
    int tid = threadIdx.x;
    #pragma unroll
    for (int i = 0; i < 16; i++) {
        int idx = tid + (i << 8);
        int d = idx & 63, r = idx >> 6;
        Qs[r][d] = qb[(size_t)(q0 + r) * D3 + d];
        Ks[r][d] = kb[(size_t)(t0 + r) * D3 + d];
    }
    __syncthreads();
    int tx = tid & 15, ty = tid >> 4;
    float acc[4][4] = {};
    #pragma unroll 8
    for (int kk = 0; kk < 64; kk++) {
        float a[4], bb[4];
        #pragma unroll
        for (int i = 0; i < 4; i++) a[i] = Qs[ty + (i << 4)][kk];
        #pragma unroll
        for (int j = 0; j < 4; j++) bb[j] = Ks[tx + (j << 4)][kk];
        #pragma unroll
        for (int i = 0; i < 4; i++)
            #pragma unroll
            for (int j = 0; j < 4; j++)
                acc[i][j] += a[i] * bb[j];
    }
    #pragma unroll
    for (int j = 0; j < 4; j++) {
        int t = t0 + tx + (j << 4);
        float biasv = (1.0f - (float)mask[b * Sq + t]) * -1e9f;
        #pragma unroll
        for (int i = 0; i < 4; i++) {
            int q = q0 + ty + (i << 4);
            att[((size_t)bh * Sq + q) * Sq + t] = acc[i][j] * 0.125f + biasv;
        }
    }
}

// ---------------- row softmax over 512 ----------------
__global__ void softmax512_kernel(float* __restrict__ att) {
    size_t row = blockIdx.x;
    float* p = att + row * Sq;
    int tid = threadIdx.x;   // 128 threads
    __shared__ float scratch[32];
    float v[4];
    float m = -INFINITY;
    #pragma unroll
    for (int i = 0; i < 4; i++) { v[i] = p[tid + i * 128]; m = fmaxf(m, v[i]); }
    m = block_reduce_max(m, scratch);
    float s = 0.f;
    #pragma unroll
    for (int i = 0; i < 4; i++) { v[i] = __expf(v[i] - m); s += v[i]; }
    s = block_reduce_sum(s, scratch);
    float inv = 1.0f / s;
    #pragma unroll
    for (int i = 0; i < 4; i++) p[tid + i * 128] = v[i] * inv;
}

// ---------------- context: ctx[b,q, h*64+d] = sum_t att * v ----------------
__global__ void attn_ctx_kernel(const float* __restrict__ att,
                                const float* __restrict__ qkv,
                                float* __restrict__ ctx) {
    int bh = blockIdx.y;
    int b = bh / Hq, h = bh % Hq;
    int q0 = blockIdx.x << 6;
    const float* A = att + (size_t)bh * Sq * Sq;
    const float* vb = qkv + (size_t)b * Sq * D3 + 2 * Dq + h * HDq;
    __shared__ float As[16][64];
    __shared__ float Vs[16][64];
    int tid = threadIdx.x;
    int tx = tid & 15, ty = tid >> 4;
    float acc[4][4] = {};
    for (int t0 = 0; t0 < Sq; t0 += 16) {
        #pragma unroll
        for (int i = 0; i < 4; i++) {
            int idx = tid + (i << 8);
            int kk = idx & 15, mm = idx >> 4;
            As[kk][mm] = A[(size_t)(q0 + mm) * Sq + t0 + kk];
            int nn = idx & 63, k2 = idx >> 6;
            Vs[k2][nn] = vb[(size_t)(t0 + k2) * D3 + nn];
        }
        __syncthreads();
        #pragma unroll
        for (int kk = 0; kk < 16; kk++) {
            float a[4], bb[4];
            #pragma unroll
            for (int i = 0; i < 4; i++) a[i] = As[kk][ty + (i << 4)];
            #pragma unroll
            for (int j = 0; j < 4; j++) bb[j] = Vs[kk][tx + (j << 4)];
            #pragma unroll
            for (int i = 0; i < 4; i++)
                #pragma unroll
                for (int j = 0; j < 4; j++)
                    acc[i][j] += a[i] * bb[j];
        }
        __syncthreads();
    }
    #pragma unroll
    for (int i = 0; i < 4; i++) {
        int q = q0 + ty + (i << 4);
        #pragma unroll
        for (int j = 0; j < 4; j++)
            ctx[((size_t)b * Sq + q) * Dq + h * HDq + tx + (j << 4)] = acc[i][j];
    }
}

// ---------------- logits: x[Mtok,768] @ Wcls[768,9] + bcls ----------------
__global__ void logits_kernel(const float* __restrict__ x,
                              const float* __restrict__ Wc,
                              const float* __restrict__ bc,
                              float* __restrict__ lg) {
    int row = blockIdx.x;
    __shared__ float buf[Dq];
    for (int d = threadIdx.x; d < Dq; d += blockDim.x)
        buf[d] = x[(size_t)row * Dq + d];
    __syncthreads();
    int w = threadIdx.x >> 5, lane = threadIdx.x & 31;  // 9 warps
    if (w < NK) {
        float s = 0.f;
        for (int d = lane; d < Dq; d += 32) s += buf[d] * Wc[d * NK + w];
        #pragma unroll
        for (int o = 16; o > 0; o >>= 1) s += __shfl_down_sync(0xffffffffu, s, o);
        if (lane == 0) lg[(size_t)row * NK + w] = s + bc[w];
    }
}

// ---------------- CRF gold-path score per batch ----------------
__global__ void crf_score_kernel(const float* __restrict__ lg,
                                 const int* __restrict__ labels,
                                 const int* __restrict__ mask,
                                 const float* __restrict__ st,
                                 const float* __restrict__ en,
                                 const float* __restrict__ tr,
                                 float* __restrict__ sc) {
    int b = blockIdx.x;
    const int* lab = labels + b * Sq;
    const int* mk = mask + b * Sq;
    __shared__ float scratch[32];
    float lsum = 0.f; float lcnt = 0.f;
    for (int t = threadIdx.x; t < Sq; t += blockDim.x) {
        lcnt += (float)mk[t];
        if (t >= 1) {
            float e = lg[((size_t)b * Sq + t) * NK + lab[t]];
            float trv = tr[lab[t - 1] * NK + lab[t]];
            lsum += (float)mk[t] * (trv + e);
        }
    }
    float tot = block_reduce_sum(lsum, scratch);
    float cnt = block_reduce_sum(lcnt, scratch);
    if (threadIdx.x == 0) {
        int last = (int)(cnt + 0.5f) - 1;
        sc[b] = st[lab[0]] + lg[((size_t)b * Sq) * NK + lab[0]] + tot + en[lab[last]];
    }
}

// ---------------- CRF forward (logZ) + final scalar ----------------
__global__ void crf_forward_kernel(const float* __restrict__ lg,
                                   const int* __restrict__ mask,
                                   const float* __restrict__ st,
                                   const float* __restrict__ en,
                                   const float* __restrict__ tr,
                                   const float* __restrict__ sc,
                                   float* __restrict__ out) {
    __shared__ float sal[Bq][12];
    __shared__ float strn[NK * NK];
    __shared__ float sst[NK], sen[NK];
    __shared__ float slz[Bq];
    int tid = threadIdx.x;  // 512 threads = 16 warps, one per batch
    if (tid < NK * NK) strn[tid] = tr[tid];
    if (tid < NK) { sst[tid] = st[tid]; sen[tid] = en[tid]; }
    __syncthreads();
    int b = tid >> 5, j = tid & 31;
    int jj = (j < NK) ? j : 0;
    if (j < NK) sal[b][j] = sst[j] + lg[((size_t)b * Sq) * NK + j];
    __syncwarp();
    for (int t = 1; t < Sq; t++) {
        float a[NK];
        #pragma unroll
        for (int i = 0; i < NK; i++) a[i] = sal[b][i];
        float m = -INFINITY;
        #pragma unroll
        for (int i = 0; i < NK; i++) m = fmaxf(m, a[i] + strn[i * NK + jj]);
        float s = 0.f;
        #pragma unroll
        for (int i = 0; i < NK; i++) s += expf(a[i] + strn[i * NK + jj] - m);
        float nxt = m + logf(s) + lg[((size_t)b * Sq + t) * NK + jj];
        int mt = mask[b * Sq + t];
        float newv = (mt > 0) ? nxt : a[jj];
        __syncwarp();
        if (j < NK) sal[b][j] = newv;
        __syncwarp();
    }
    float v = (j < NK) ? (sal[b][jj] + sen[jj]) : -INFINITY;
    float m = v;
    #pragma unroll
    for (int o = 16; o > 0; o >>= 1) m = fmaxf(m, __shfl_xor_sync(0xffffffffu, m, o));
    float s = (j < NK) ? expf(v - m) : 0.f;
    #pragma unroll
    for (int o = 16; o > 0; o >>= 1) s += __shfl_xor_sync(0xffffffffu, s, o);
    if (j == 0) slz[b] = m + logf(s);
    __syncthreads();
    if (tid == 0) {
        float o = 0.f;
        for (int b2 = 0; b2 < Bq; b2++) o += slz[b2] - sc[b2];
        out[0] = o;
    }
}

// ---------------- host launch ----------------
extern "C" void kernel_launch(void* const* d_in, const int* in_sizes, int n_in,
                              void* d_out, int out_size) {
    const int*   input_ids = (const int*)d_in[0];
    const int*   amask     = (const int*)d_in[1];
    const int*   labels    = (const int*)d_in[2];
    const float* emb   = (const float*)d_in[3];
    const float* pos   = (const float*)d_in[4];
    const float* lng   = (const float*)d_in[5];
    const float* lnb   = (const float*)d_in[6];
    const float* Wqkv  = (const float*)d_in[7];
    const float* bqkv  = (const float*)d_in[8];
    const float* Wo    = (const float*)d_in[9];
    const float* bo    = (const float*)d_in[10];
    const float* ln1g  = (const float*)d_in[11];
    const float* ln1b  = (const float*)d_in[12];
    const float* W1    = (const float*)d_in[13];
    const float* b1    = (const float*)d_in[14];
    const float* W2    = (const float*)d_in[15];
    const float* b2    = (const float*)d_in[16];
    const float* ln2g  = (const float*)d_in[17];
    const float* ln2b  = (const float*)d_in[18];
    const float* Wcls  = (const float*)d_in[19];
    const float* bcls  = (const float*)d_in[20];
    const float* st    = (const float*)d_in[21];
    const float* en    = (const float*)d_in[22];
    const float* tr    = (const float*)d_in[23];
    float* out = (float*)d_out;

    float *x, *qkv, *att, *ctx, *proj, *hbuf, *lg, *sc;
    cudaGetSymbolAddress((void**)&x,    g_x);
    cudaGetSymbolAddress((void**)&qkv,  g_qkv);
    cudaGetSymbolAddress((void**)&att,  g_att);
    cudaGetSymbolAddress((void**)&ctx,  g_ctx);
    cudaGetSymbolAddress((void**)&proj, g_proj);
    cudaGetSymbolAddress((void**)&hbuf, g_h);
    cudaGetSymbolAddress((void**)&lg,   g_lg);
    cudaGetSymbolAddress((void**)&sc,   g_sc);

    embed_ln_kernel<<<Mtok, 256>>>(input_ids, emb, pos, lng, lnb, x);

    for (int l = 0; l < Lq; l++) {
        gemm_bf16<<<dim3(D3 / GBN, Mtok / GBM), 256>>>(
            x, Wqkv + (size_t)l * Dq * D3, bqkv + l * D3, qkv, Mtok, D3, Dq, 0);
        attn_scores_kernel<<<dim3(Sq / 64, Sq / 64, Bq * Hq), 256>>>(qkv, amask, att);
        softmax512_kernel<<<Bq * Hq * Sq, 128>>>(att);
        attn_ctx_kernel<<<dim3(Sq / 64, Bq * Hq), 256>>>(att, qkv, ctx);
        gemm_bf16<<<dim3(Dq / GBN, Mtok / GBM), 256>>>(
            ctx, Wo + (size_t)l * Dq * Dq, bo + l * Dq, proj, Mtok, Dq, Dq, 0);
        add_ln_kernel<<<Mtok, 256>>>(x, proj, ln1g + l * Dq, ln1b + l * Dq, x);
        gemm_bf16<<<dim3(Fq / GBN, Mtok / GBM), 256>>>(
            x, W1 + (size_t)l * Dq * Fq, b1 + l * Fq, hbuf, Mtok, Fq, Dq, 1);
        gemm_bf16<<<dim3(Dq / GBN, Mtok / GBM), 256>>>(
            hbuf, W2 + (size_t)l * Fq * Dq, b2 + l * Dq, proj, Mtok, Dq, Fq, 0);
        add_ln_kernel<<<Mtok, 256>>>(x, proj, ln2g + l * Dq, ln2b + l * Dq, x);
    }

    logits_kernel<<<Mtok, 288>>>(x, Wcls, bcls, lg);
    crf_score_kernel<<<Bq, 256>>>(lg, labels, amask, st, en, tr, sc);
    crf_forward_kernel<<<1, 512>>>(lg, amask, st, en, tr, sc, out);
}